// round 6
// baseline (speedup 1.0000x reference)
#include <cuda_runtime.h>

// Problem constants
#define B_   32
#define TQ_  1024
#define TK_  1024
#define DK_  64
#define NTHREADS 512

// smem layout (floats): sQ[2048] | sS[32*1024] | sKV[4*4096] (2 dbl-buffers per group)
#define SS_OFF   2048
#define SKV_OFF  (SS_OFF + 32 * 1024)
#define SMEM_FLOATS (SKV_OFF + 4 * 4096)
#define SMEM_BYTES  (SMEM_FLOATS * 4)      // 200 KB

// Packed f32x2 FMA (Blackwell dual-issue fp32 path)
__device__ __forceinline__ void ffma2(float2 &d, const float2 a, const float2 b) {
    unsigned long long &dd = reinterpret_cast<unsigned long long &>(d);
    asm("fma.rn.f32x2 %0, %1, %2, %0;"
        : "+l"(dd)
        : "l"(reinterpret_cast<const unsigned long long &>(a)),
          "l"(reinterpret_cast<const unsigned long long &>(b)));
}

__device__ __forceinline__ void gbar(int g) {   // per-group named barrier (256 threads)
    asm volatile("bar.sync %0, 256;" :: "r"(g + 1) : "memory");
}

__global__ void __launch_bounds__(NTHREADS, 1)
mha_fused_kernel(const float* __restrict__ Kg, const float* __restrict__ Vg,
                 const float* __restrict__ Qg, const int* __restrict__ Mg,
                 const float* __restrict__ QMg,
                 float* __restrict__ outR, float* __restrict__ outA)
{
    extern __shared__ float sm[];
    float* sQ  = sm;
    float* sS  = sm + SS_OFF;
    float* sKV = sm + SKV_OFF;

    const int tid = threadIdx.x;
    const int b   = blockIdx.x >> 5;
    const int q0  = (blockIdx.x & 31) * 32;

    const float* gQ = Qg + ((size_t)b * TQ_ + q0) * DK_;
    const float* gK = Kg + (size_t)b * TK_ * DK_;
    const float* gV = Vg + (size_t)b * TK_ * DK_;

    const int w   = tid >> 5;       // 16 warps
    const int ln  = tid & 31;
    const int g   = w >> 3;         // group 0: even k-tiles, group 1: odd k-tiles
    const int wg  = w & 7;          // warp-in-group -> q rows 4wg..4wg+3
    const int tg  = tid & 255;      // thread-in-group
    const int kk  = ln & 7;
    const int dd  = ln >> 3;

    float* bufs = sKV + g * 8192;   // this group's two 4096-float buffers

    // ---- stage Q (once) ----
    for (int i = tid; i < 512; i += NTHREADS)
        ((float4*)sQ)[i] = ((const float4*)gQ)[i];

    // ---- prefetch this group's first K tile (tile index g) ----
    float4 pref[4];
    #pragma unroll
    for (int p = 0; p < 4; p++) {
        int idx = tg + p * 256, row = idx >> 4, c = idx & 15;
        pref[p] = *(const float4*)(gK + (size_t)g * 4096 + row * 64 + c * 4);
    }
    __syncthreads();   // sQ visible

    // ---- Q in registers: 4 rows x 16-d slice ----
    float2 q2[4][8];
    #pragma unroll
    for (int i = 0; i < 4; i++) {
        #pragma unroll
        for (int j = 0; j < 8; j++)
            q2[i][j] = *(const float2*)(sQ + (4*wg + i) * 64 + dd * 16 + 2 * j);
    }

    // swizzled read offsets: d4 = 4*dd+u, off = (d4 ^ kk) words *4B
    int uoff[4];
    #pragma unroll
    for (int u = 0; u < 4; u++) uoff[u] = ((4 * dd + u) ^ kk) << 2;

    // =========================== QK^T (8 tiles per group) ===========================
    for (int it = 0; it < 8; it++) {
        const int t = 2 * it + g;                 // this group's tile
        float* kb = bufs + (it & 1) * 4096;
        #pragma unroll
        for (int p = 0; p < 4; p++) {
            int idx = tg + p * 256, row = idx >> 4, c = idx & 15;
            *(float4*)(kb + row * 64 + ((c ^ (row & 7)) << 2)) = pref[p];
        }
        gbar(g);
        if (it + 1 < 8) {
            #pragma unroll
            for (int p = 0; p < 4; p++) {
                int idx = tg + p * 256, row = idx >> 4, c = idx & 15;
                pref[p] = *(const float4*)(gK + (size_t)(t + 2) * 4096 + row * 64 + c * 4);
            }
        }
        #pragma unroll
        for (int pass = 0; pass < 2; pass++) {
            float2 acc[4][4];
            #pragma unroll
            for (int i = 0; i < 4; i++) {
                #pragma unroll
                for (int r = 0; r < 4; r++) acc[i][r] = make_float2(0.f, 0.f);
            }
            #pragma unroll
            for (int rr = 0; rr < 4; rr++) {
                const float* kbase = kb + (kk + 8 * (pass * 4 + rr)) * 64;
                #pragma unroll
                for (int u = 0; u < 4; u++) {
                    float4 kv = *(const float4*)(kbase + uoff[u]);
                    #pragma unroll
                    for (int i = 0; i < 4; i++) {
                        ffma2(acc[i][rr], q2[i][2*u],     make_float2(kv.x, kv.y));
                        ffma2(acc[i][rr], q2[i][2*u + 1], make_float2(kv.z, kv.w));
                    }
                }
            }
            #pragma unroll
            for (int i = 0; i < 4; i++) {
                float v0 = acc[i][0].x + acc[i][0].y;
                float v1 = acc[i][1].x + acc[i][1].y;
                float v2 = acc[i][2].x + acc[i][2].y;
                float v3 = acc[i][3].x + acc[i][3].y;
                v0 += __shfl_xor_sync(0xffffffffu, v0, 8);
                v0 += __shfl_xor_sync(0xffffffffu, v0, 16);
                v1 += __shfl_xor_sync(0xffffffffu, v1, 8);
                v1 += __shfl_xor_sync(0xffffffffu, v1, 16);
                v2 += __shfl_xor_sync(0xffffffffu, v2, 8);
                v2 += __shfl_xor_sync(0xffffffffu, v2, 16);
                v3 += __shfl_xor_sync(0xffffffffu, v3, 8);
                v3 += __shfl_xor_sync(0xffffffffu, v3, 16);
                float vs = (dd == 0) ? v0 : (dd == 1) ? v1 : (dd == 2) ? v2 : v3;
                sS[(4*wg + i) * 1024 + t * 64 + kk + 8 * (pass * 4 + dd)] = vs * 0.125f;
            }
        }
    }

    // ---- prefetch this group's first V tile (overlaps softmax tail) ----
    #pragma unroll
    for (int p = 0; p < 4; p++) {
        int idx = tg + p * 256, row = idx >> 4, c = idx & 15;
        pref[p] = *(const float4*)(gV + (size_t)g * 4096 + row * 64 + c * 4);
    }
    __syncthreads();   // all scores written (both groups)

    // =========================== softmax: warp w -> rows 2w, 2w+1 ===========================
    #pragma unroll 1
    for (int rr = 0; rr < 2; rr++) {
        const int q  = 2 * w + rr;
        const int qg = q0 + q;
        const int* mrow = Mg + ((size_t)b * TQ_ + qg) * TK_;
        float* srow = sS + q * TK_;
        float4 sv[8];
        unsigned mb = 0u;
        float mx = -3.0e38f;
        #pragma unroll
        for (int i = 0; i < 8; i++) {
            sv[i] = *(const float4*)(srow + i * 128 + 4 * ln);
            int4 m = *(const int4*)(mrow + i * 128 + 4 * ln);
            unsigned bits = (m.x ? 1u : 0u) | (m.y ? 2u : 0u) | (m.z ? 4u : 0u) | (m.w ? 8u : 0u);
            mb |= bits << (4 * i);
            if (!m.x) mx = fmaxf(mx, sv[i].x);
            if (!m.y) mx = fmaxf(mx, sv[i].y);
            if (!m.z) mx = fmaxf(mx, sv[i].z);
            if (!m.w) mx = fmaxf(mx, sv[i].w);
        }
        #pragma unroll
        for (int o = 16; o > 0; o >>= 1) mx = fmaxf(mx, __shfl_xor_sync(0xffffffffu, mx, o));
        float sum = 0.f;
        #pragma unroll
        for (int i = 0; i < 8; i++) {
            float p0 = ((mb >> (4*i)) & 1u) ? 0.f : __expf(sv[i].x - mx);
            float p1 = ((mb >> (4*i + 1)) & 1u) ? 0.f : __expf(sv[i].y - mx);
            float p2 = ((mb >> (4*i + 2)) & 1u) ? 0.f : __expf(sv[i].z - mx);
            float p3 = ((mb >> (4*i + 3)) & 1u) ? 0.f : __expf(sv[i].w - mx);
            sv[i] = make_float4(p0, p1, p2, p3);
            sum += (p0 + p1) + (p2 + p3);
        }
        #pragma unroll
        for (int o = 16; o > 0; o >>= 1) sum += __shfl_xor_sync(0xffffffffu, sum, o);

        const float qm = QMg[(size_t)b * TQ_ + qg];
        const bool allmask = !(sum > 0.f);        // fully-masked row -> uniform softmax
        const float scale = allmask ? 0.f : (qm / sum);
        const float uni   = qm * (1.0f / 1024.0f);
        float* arow = outA + ((size_t)b * TQ_ + qg) * TK_;
        #pragma unroll
        for (int i = 0; i < 8; i++) {
            float4 v;
            v.x = allmask ? uni : sv[i].x * scale;
            v.y = allmask ? uni : sv[i].y * scale;
            v.z = allmask ? uni : sv[i].z * scale;
            v.w = allmask ? uni : sv[i].w * scale;
            *(float4*)(srow + i * 128 + 4 * ln) = v;   // reused by PV
            *(float4*)(arow + i * 128 + 4 * ln) = v;   // attn output
        }
    }
    __syncthreads();   // scores final before PV reads cross-warp rows

    // =========================== PV (8 tiles per group, partial over k-half) ===========================
    float2 acc[4][8];
    #pragma unroll
    for (int i = 0; i < 4; i++) {
        #pragma unroll
        for (int j = 0; j < 8; j++) acc[i][j] = make_float2(0.f, 0.f);
    }

    for (int it = 0; it < 8; it++) {
        const int t = 2 * it + g;
        float* vb = bufs + (it & 1) * 4096;
        #pragma unroll
        for (int p = 0; p < 4; p++) {
            int idx = tg + p * 256, row = idx >> 4, c = idx & 15;
            *(float4*)(vb + row * 64 + ((c ^ (row & 7)) << 2)) = pref[p];
        }
        gbar(g);
        if (it + 1 < 8) {
            #pragma unroll
            for (int p = 0; p < 4; p++) {
                int idx = tg + p * 256, row = idx >> 4, c = idx & 15;
                pref[p] = *(const float4*)(gV + (size_t)(t + 2) * 4096 + row * 64 + c * 4);
            }
        }
        #pragma unroll
        for (int r = 0; r < 8; r++) {
            const int kt = kk + 8 * r;
            const float* vbase = vb + kt * 64;
            float4 vv0 = *(const float4*)(vbase + uoff[0]);
            float4 vv1 = *(const float4*)(vbase + uoff[1]);
            float4 vv2 = *(const float4*)(vbase + uoff[2]);
            float4 vv3 = *(const float4*)(vbase + uoff[3]);
            #pragma unroll
            for (int i = 0; i < 4; i++) {
                float s = sS[(4*wg + i) * 1024 + t * 64 + kt];   // broadcast LDS
                float2 s2 = make_float2(s, s);
                ffma2(acc[i][0], s2, make_float2(vv0.x, vv0.y));
                ffma2(acc[i][1], s2, make_float2(vv0.z, vv0.w));
                ffma2(acc[i][2], s2, make_float2(vv1.x, vv1.y));
                ffma2(acc[i][3], s2, make_float2(vv1.z, vv1.w));
                ffma2(acc[i][4], s2, make_float2(vv2.x, vv2.y));
                ffma2(acc[i][5], s2, make_float2(vv2.z, vv2.w));
                ffma2(acc[i][6], s2, make_float2(vv3.x, vv3.y));
                ffma2(acc[i][7], s2, make_float2(vv3.z, vv3.w));
            }
        }
    }

    // in-warp reduce over the 8 kk-lanes
    #pragma unroll
    for (int i = 0; i < 4; i++) {
        #pragma unroll
        for (int j = 0; j < 8; j++) {
            float x = acc[i][j].x, y = acc[i][j].y;
            x += __shfl_xor_sync(0xffffffffu, x, 1);
            y += __shfl_xor_sync(0xffffffffu, y, 1);
            x += __shfl_xor_sync(0xffffffffu, x, 2);
            y += __shfl_xor_sync(0xffffffffu, y, 2);
            x += __shfl_xor_sync(0xffffffffu, x, 4);
            y += __shfl_xor_sync(0xffffffffu, y, 4);
            acc[i][j] = make_float2(x, y);
        }
    }

    // cross-group reduce through smem scratch (reuse sKV[0..4095] after barrier)
    float* scratch = sKV;
    __syncthreads();   // all PV compute done; buffers reusable
    #pragma unroll
    for (int i = 0; i < 4; i++) {
        float rx = acc[i][0].x, ry = acc[i][0].y;
        #pragma unroll
        for (int j = 1; j < 8; j++) {
            if (kk == j) { rx = acc[i][j].x; ry = acc[i][j].y; }
        }
        // scratch[(g*32 + row)*64 + d], d = 16*dd + 2*kk
        *(float2*)(scratch + ((g * 32 + 4*wg + i) * 64) + 16 * dd + 2 * kk) = make_float2(rx, ry);
    }
    __syncthreads();

    // warp w sums rows 2w, 2w+1 across groups and stores
    #pragma unroll
    for (int rr = 0; rr < 2; rr++) {
        const int q = 2 * w + rr;
        float2 a0 = *(const float2*)(scratch + q * 64 + 2 * ln);
        float2 a1 = *(const float2*)(scratch + (32 + q) * 64 + 2 * ln);
        float2 r  = make_float2(a0.x + a1.x, a0.y + a1.y);
        *(float2*)(outR + ((size_t)b * TQ_ + q0 + q) * DK_ + 2 * ln) = r;
    }
}

extern "C" void kernel_launch(void* const* d_in, const int* in_sizes, int n_in,
                              void* d_out, int out_size)
{
    const float* Kg  = (const float*)d_in[0];
    const float* Vg  = (const float*)d_in[1];
    const float* Qg  = (const float*)d_in[2];
    const int*   Mg  = (const int*)d_in[3];
    const float* QMg = (const float*)d_in[4];

    float* outR = (float*)d_out;                       // result [B, TQ, DK]
    float* outA = outR + (size_t)B_ * TQ_ * DK_;       // attn   [B, TQ, TK]

    cudaFuncSetAttribute(mha_fused_kernel,
                         cudaFuncAttributeMaxDynamicSharedMemorySize, SMEM_BYTES);

    dim3 grid(B_ * 32);   // 1024 CTAs
    mha_fused_kernel<<<grid, NTHREADS, SMEM_BYTES>>>(Kg, Vg, Qg, Mg, QMg, outR, outA);
}

// round 8
// speedup vs baseline: 1.6612x; 1.6612x over previous
#include <cuda_runtime.h>
#include <cuda_bf16.h>
#include <cstdint>

#define B_ 32
// smem byte offsets
#define OFF_RED   0
#define OFF_SCL   1024
#define OFF_UNI   1536
#define OFF_QH    2048
#define OFF_QL    18432
#define OFF_KH    34816
#define OFF_KL    51200
#define OFF_MASK  67584
#define OFF_OST   2048
#define SMEM_TOTAL 83968

__device__ __forceinline__ uint32_t s2u(const void* p){
    uint32_t a; asm("{ .reg .u64 t; cvta.to.shared.u64 t, %1; cvt.u32.u64 %0, t; }":"=r"(a):"l"(p)); return a;
}
__device__ __forceinline__ void ldsm4(uint32_t* r, uint32_t a){
    asm volatile("ldmatrix.sync.aligned.m8n8.x4.shared.b16 {%0,%1,%2,%3}, [%4];"
        :"=r"(r[0]),"=r"(r[1]),"=r"(r[2]),"=r"(r[3]):"r"(a));
}
__device__ __forceinline__ void ldsm4t(uint32_t* r, uint32_t a){
    asm volatile("ldmatrix.sync.aligned.m8n8.x4.trans.shared.b16 {%0,%1,%2,%3}, [%4];"
        :"=r"(r[0]),"=r"(r[1]),"=r"(r[2]),"=r"(r[3]):"r"(a));
}
__device__ __forceinline__ void mma_bf16(float* c, const uint32_t* a, const uint32_t* b){
    asm volatile("mma.sync.aligned.m16n8k16.row.col.f32.bf16.bf16.f32 "
        "{%0,%1,%2,%3}, {%4,%5,%6,%7}, {%8,%9}, {%0,%1,%2,%3};"
        :"+f"(c[0]),"+f"(c[1]),"+f"(c[2]),"+f"(c[3])
        :"r"(a[0]),"r"(a[1]),"r"(a[2]),"r"(a[3]),"r"(b[0]),"r"(b[1]));
}
// swizzled address of 16B unit u in row (128B rows)
__device__ __forceinline__ uint32_t swa(uint32_t base, int row, int u){
    return base + (uint32_t)row*128u + (uint32_t)(((u ^ (row & 7)) << 4));
}
__device__ __forceinline__ void split2(float x, float y, uint32_t &hi, uint32_t &lo){
    __nv_bfloat16 hx=__float2bfloat16(x), hy=__float2bfloat16(y);
    __nv_bfloat16 lx=__float2bfloat16(x-__bfloat162float(hx)), ly=__float2bfloat16(y-__bfloat162float(hy));
    hi = ((uint32_t)__bfloat16_as_ushort(hy)<<16)|__bfloat16_as_ushort(hx);
    lo = ((uint32_t)__bfloat16_as_ushort(ly)<<16)|__bfloat16_as_ushort(lx);
}
// fp32 float4 -> bf16 hi/lo split into swizzled tile
__device__ __forceinline__ void cvt_store(float4 v, char* smc, int offH, int offL, int row, int c4){
    uint32_t o = (uint32_t)row*128u + (uint32_t)(((((c4>>1) ^ (row&7)) << 4)) | ((c4&1)<<3));
    uint32_t h0, l0, h1, l1;
    split2(v.x, v.y, h0, l0);
    split2(v.z, v.w, h1, l1);
    *(uint2*)(smc + offH + o) = make_uint2(h0, h1);
    *(uint2*)(smc + offL + o) = make_uint2(l0, l1);
}

__global__ void __launch_bounds__(512, 1)
mha_hmma(const float* __restrict__ Kg, const float* __restrict__ Vg,
         const float* __restrict__ Qg, const int* __restrict__ Mg,
         const float* __restrict__ QMg, float* __restrict__ outR, float* __restrict__ outA)
{
    extern __shared__ char smc[];
    const uint32_t sb = s2u(smc);
    const int tid = threadIdx.x, wid = tid>>5, ln = tid&31;
    const int mt = wid>>1, h = wid&1;           // m-tile (16 rows), k-half
    const int la = ln&3;
    const int r0 = 16*mt + (ln>>2), r1 = r0 + 8;
    const int b = blockIdx.x>>3, q0 = (blockIdx.x&7)*128;

    // ---- prologue: Q (x0.125) -> bf16 split; mask -> bitmask [q][32 words] ----
    const float4* gQ4 = (const float4*)(Qg + ((size_t)(b*1024 + q0))*64);
    for (int i = tid; i < 2048; i += 512){
        float4 v = gQ4[i];
        v.x*=0.125f; v.y*=0.125f; v.z*=0.125f; v.w*=0.125f;
        cvt_store(v, smc, OFF_QH, OFF_QL, i>>4, i&15);
    }
    uint32_t* mbm = (uint32_t*)(smc + OFF_MASK);
    const int* gM = Mg + ((size_t)(b*1024 + q0))*1024;
    for (int i = tid; i < 4096; i += 512){
        const int4* mp = (const int4*)(gM + ((size_t)(i>>5))*1024 + (i&31)*32);
        uint32_t bits = 0;
        #pragma unroll
        for (int m2 = 0; m2 < 8; m2++){
            int4 v = mp[m2];
            bits |= ((v.x?1u:0u)|(v.y?2u:0u)|(v.z?4u:0u)|(v.w?8u:0u)) << (4*m2);
        }
        mbm[i] = bits;
    }
    const float* gK = Kg + (size_t)b*65536;
    const float* gV = Vg + (size_t)b*65536;

    // ================= pass 1: masked rowsums =================
    float rs0 = 0.f, rs1 = 0.f;
    for (int t = 0; t < 8; t++){
        __syncthreads();
        const float4* gK4 = (const float4*)(gK + (size_t)t*8192);
        #pragma unroll
        for (int p = 0; p < 4; p++){
            int i = tid + p*512;
            cvt_store(gK4[i], smc, OFF_KH, OFF_KL, i>>4, i&15);
        }
        __syncthreads();
        float s[8][4];
        #pragma unroll
        for (int j=0;j<8;j++){ s[j][0]=0.f; s[j][1]=0.f; s[j][2]=0.f; s[j][3]=0.f; }
        #pragma unroll
        for (int c = 0; c < 4; c++){
            uint32_t qh[4], ql[4];
            int qrow = 16*mt + (ln&15), qu = 2*c + (ln>>4);
            ldsm4(qh, swa(sb+OFF_QH, qrow, qu));
            ldsm4(ql, swa(sb+OFF_QL, qrow, qu));
            #pragma unroll
            for (int jp = 0; jp < 4; jp++){
                uint32_t bh[4], bl[4];
                int krow = 64*h + 16*jp + ((ln>>4)<<3) + (ln&7);
                int ku = 2*c + ((ln>>3)&1);
                ldsm4(bh, swa(sb+OFF_KH, krow, ku));
                ldsm4(bl, swa(sb+OFF_KL, krow, ku));
                mma_bf16(s[2*jp],   qh, bh);   mma_bf16(s[2*jp],   qh, bl);   mma_bf16(s[2*jp],   ql, bh);
                mma_bf16(s[2*jp+1], qh, bh+2); mma_bf16(s[2*jp+1], qh, bl+2); mma_bf16(s[2*jp+1], ql, bh+2);
            }
        }
        uint4 m0v = ((const uint4*)(mbm + r0*32))[t];
        uint4 m1v = ((const uint4*)(mbm + r1*32))[t];
        uint32_t w00 = h ? m0v.z : m0v.x, w01 = h ? m0v.w : m0v.y;
        uint32_t w10 = h ? m1v.z : m1v.x, w11 = h ? m1v.w : m1v.y;
        #pragma unroll
        for (int j = 0; j < 8; j++){
            uint32_t wr0 = (j<4)?w00:w01, wr1 = (j<4)?w10:w11;
            int bit = 8*(j&3) + 2*la;
            rs0 += ((wr0>>bit)&1u)     ? 0.f : __expf(s[j][0]);
            rs0 += ((wr0>>(bit+1))&1u) ? 0.f : __expf(s[j][1]);
            rs1 += ((wr1>>bit)&1u)     ? 0.f : __expf(s[j][2]);
            rs1 += ((wr1>>(bit+1))&1u) ? 0.f : __expf(s[j][3]);
        }
    }
    rs0 += __shfl_xor_sync(~0u, rs0, 1); rs0 += __shfl_xor_sync(~0u, rs0, 2);
    rs1 += __shfl_xor_sync(~0u, rs1, 1); rs1 += __shfl_xor_sync(~0u, rs1, 2);
    float* red = (float*)(smc + OFF_RED);
    if (la == 0){ red[h*128 + r0] = rs0; red[h*128 + r1] = rs1; }
    __syncthreads();
    if (tid < 128){
        float ssum = red[tid] + red[128+tid];
        float qm = QMg[(size_t)(b*1024 + q0 + tid)];
        ((float*)(smc+OFF_SCL))[tid] = (ssum>0.f) ? (qm/ssum) : 0.f;
        ((float*)(smc+OFF_UNI))[tid] = (ssum>0.f) ? 0.f : qm*(1.f/1024.f);
    }
    __syncthreads();
    const float scl0 = ((float*)(smc+OFF_SCL))[r0], uad0 = ((float*)(smc+OFF_UNI))[r0];
    const float scl1 = ((float*)(smc+OFF_SCL))[r1], uad1 = ((float*)(smc+OFF_UNI))[r1];

    // ================= pass 2: attn + PV =================
    float o[8][4];
    #pragma unroll
    for (int j=0;j<8;j++){ o[j][0]=0.f; o[j][1]=0.f; o[j][2]=0.f; o[j][3]=0.f; }

    for (int t = 0; t < 8; t++){
        __syncthreads();
        const float4* gK4 = (const float4*)(gK + (size_t)t*8192);
        #pragma unroll
        for (int p = 0; p < 4; p++){
            int i = tid + p*512;
            cvt_store(gK4[i], smc, OFF_KH, OFF_KL, i>>4, i&15);
        }
        __syncthreads();
        float s[8][4];
        #pragma unroll
        for (int j=0;j<8;j++){ s[j][0]=0.f; s[j][1]=0.f; s[j][2]=0.f; s[j][3]=0.f; }
        #pragma unroll
        for (int c = 0; c < 4; c++){
            uint32_t qh[4], ql[4];
            int qrow = 16*mt + (ln&15), qu = 2*c + (ln>>4);
            ldsm4(qh, swa(sb+OFF_QH, qrow, qu));
            ldsm4(ql, swa(sb+OFF_QL, qrow, qu));
            #pragma unroll
            for (int jp = 0; jp < 4; jp++){
                uint32_t bh[4], bl[4];
                int krow = 64*h + 16*jp + ((ln>>4)<<3) + (ln&7);
                int ku = 2*c + ((ln>>3)&1);
                ldsm4(bh, swa(sb+OFF_KH, krow, ku));
                ldsm4(bl, swa(sb+OFF_KL, krow, ku));
                mma_bf16(s[2*jp],   qh, bh);   mma_bf16(s[2*jp],   qh, bl);   mma_bf16(s[2*jp],   ql, bh);
                mma_bf16(s[2*jp+1], qh, bh+2); mma_bf16(s[2*jp+1], qh, bl+2); mma_bf16(s[2*jp+1], ql, bh+2);
            }
        }
        // exp * scale (+ uniform for all-masked rows)
        {
            uint4 m0v = ((const uint4*)(mbm + r0*32))[t];
            uint4 m1v = ((const uint4*)(mbm + r1*32))[t];
            uint32_t w00 = h ? m0v.z : m0v.x, w01 = h ? m0v.w : m0v.y;
            uint32_t w10 = h ? m1v.z : m1v.x, w11 = h ? m1v.w : m1v.y;
            #pragma unroll
            for (int j = 0; j < 8; j++){
                uint32_t wr0 = (j<4)?w00:w01, wr1 = (j<4)?w10:w11;
                int bit = 8*(j&3) + 2*la;
                float p0 = ((wr0>>bit)&1u)     ? 0.f : __expf(s[j][0]);
                float p1 = ((wr0>>(bit+1))&1u) ? 0.f : __expf(s[j][1]);
                float p2 = ((wr1>>bit)&1u)     ? 0.f : __expf(s[j][2]);
                float p3 = ((wr1>>(bit+1))&1u) ? 0.f : __expf(s[j][3]);
                s[j][0] = p0*scl0 + uad0;  s[j][1] = p1*scl0 + uad0;
                s[j][2] = p2*scl1 + uad1;  s[j][3] = p3*scl1 + uad1;
            }
        }
        // attn store (quad-contiguous 32B sectors)
        {
            float* a0p = outA + ((size_t)(b*1024+q0+r0))*1024 + t*128 + 64*h + 2*la;
            float* a1p = outA + ((size_t)(b*1024+q0+r1))*1024 + t*128 + 64*h + 2*la;
            #pragma unroll
            for (int j=0;j<8;j++){
                *(float2*)(a0p + 8*j) = make_float2(s[j][0], s[j][1]);
                *(float2*)(a1p + 8*j) = make_float2(s[j][2], s[j][3]);
            }
        }
        // build P A-fragments (hi/lo) in registers
        uint32_t Ah[4][4], Al[4][4];
        #pragma unroll
        for (int c=0;c<4;c++){
            split2(s[2*c][0],   s[2*c][1],   Ah[c][0], Al[c][0]);
            split2(s[2*c][2],   s[2*c][3],   Ah[c][1], Al[c][1]);
            split2(s[2*c+1][0], s[2*c+1][1], Ah[c][2], Al[c][2]);
            split2(s[2*c+1][2], s[2*c+1][3], Ah[c][3], Al[c][3]);
        }
        __syncthreads();   // K smem free
        const float4* gV4 = (const float4*)(gV + (size_t)t*8192);
        #pragma unroll
        for (int p = 0; p < 4; p++){
            int i = tid + p*512;
            cvt_store(gV4[i], smc, OFF_KH, OFF_KL, i>>4, i&15);   // reuse tile buffers
        }
        __syncthreads();
        #pragma unroll
        for (int c=0;c<4;c++){
            #pragma unroll
            for (int jp=0;jp<4;jp++){
                uint32_t bh[4], bl[4];
                int vrow = 64*h + 16*c + ((ln>>3)&1)*8 + (ln&7);
                int vu = 2*jp + (ln>>4);
                ldsm4t(bh, swa(sb+OFF_KH, vrow, vu));
                ldsm4t(bl, swa(sb+OFF_KL, vrow, vu));
                mma_bf16(o[2*jp],   Ah[c], bh);   mma_bf16(o[2*jp],   Ah[c], bl);   mma_bf16(o[2*jp],   Al[c], bh);
                mma_bf16(o[2*jp+1], Ah[c], bh+2); mma_bf16(o[2*jp+1], Ah[c], bl+2); mma_bf16(o[2*jp+1], Al[c], bh+2);
            }
        }
    }

    // ---- combine k-halves, store result ----
    float* Os = (float*)(smc + OFF_OST);
    __syncthreads();
    if (h == 0){
        #pragma unroll
        for (int j=0;j<8;j++){
            *(float2*)(Os + r0*64 + 8*j + 2*la) = make_float2(o[j][0], o[j][1]);
            *(float2*)(Os + r1*64 + 8*j + 2*la) = make_float2(o[j][2], o[j][3]);
        }
    }
    __syncthreads();
    if (h == 1){
        float* oR = outR + ((size_t)(b*1024+q0))*64;
        #pragma unroll
        for (int j=0;j<8;j++){
            float2 a0 = *(float2*)(Os + r0*64 + 8*j + 2*la);
            float2 a1 = *(float2*)(Os + r1*64 + 8*j + 2*la);
            *(float2*)(oR + (size_t)r0*64 + 8*j + 2*la) = make_float2(a0.x+o[j][0], a0.y+o[j][1]);
            *(float2*)(oR + (size_t)r1*64 + 8*j + 2*la) = make_float2(a1.x+o[j][2], a1.y+o[j][3]);
        }
    }
}

extern "C" void kernel_launch(void* const* d_in, const int* in_sizes, int n_in,
                              void* d_out, int out_size)
{
    const float* Kg  = (const float*)d_in[0];
    const float* Vg  = (const float*)d_in[1];
    const float* Qg  = (const float*)d_in[2];
    const int*   Mg  = (const int*)d_in[3];
    const float* QMg = (const float*)d_in[4];
    float* outR = (float*)d_out;
    float* outA = outR + (size_t)B_ * 1024 * 64;
    cudaFuncSetAttribute(mha_hmma, cudaFuncAttributeMaxDynamicSharedMemorySize, SMEM_TOTAL);
    mha_hmma<<<B_ * 8, 512, SMEM_TOTAL>>>(Kg, Vg, Qg, Mg, QMg, outR, outA);
}

// round 9
// speedup vs baseline: 1.6992x; 1.0229x over previous
#include <cuda_runtime.h>
#include <cuda_bf16.h>
#include <cstdint>

#define B_ 32
// smem byte offsets
#define OFF_RED   0
#define OFF_SCL   1024
#define OFF_UNI   1536
#define OFF_QH    2048
#define OFF_QL    18432
#define OFF_K0H   34816
#define OFF_K0L   51200
#define OFF_K1H   67584
#define OFF_K1L   83968
#define OFF_V0H   100352
#define OFF_V0L   116736
#define OFF_V1H   133120
#define OFF_V1L   149504
#define OFF_MASK  165888
#define OFF_OST   2048
#define SMEM_TOTAL 182272

__device__ __forceinline__ uint32_t s2u(const void* p){
    uint32_t a; asm("{ .reg .u64 t; cvta.to.shared.u64 t, %1; cvt.u32.u64 %0, t; }":"=r"(a):"l"(p)); return a;
}
__device__ __forceinline__ void ldsm4(uint32_t* r, uint32_t a){
    asm volatile("ldmatrix.sync.aligned.m8n8.x4.shared.b16 {%0,%1,%2,%3}, [%4];"
        :"=r"(r[0]),"=r"(r[1]),"=r"(r[2]),"=r"(r[3]):"r"(a));
}
__device__ __forceinline__ void ldsm4t(uint32_t* r, uint32_t a){
    asm volatile("ldmatrix.sync.aligned.m8n8.x4.trans.shared.b16 {%0,%1,%2,%3}, [%4];"
        :"=r"(r[0]),"=r"(r[1]),"=r"(r[2]),"=r"(r[3]):"r"(a));
}
__device__ __forceinline__ void mma_bf16(float* c, const uint32_t* a, const uint32_t* b){
    asm volatile("mma.sync.aligned.m16n8k16.row.col.f32.bf16.bf16.f32 "
        "{%0,%1,%2,%3}, {%4,%5,%6,%7}, {%8,%9}, {%0,%1,%2,%3};"
        :"+f"(c[0]),"+f"(c[1]),"+f"(c[2]),"+f"(c[3])
        :"r"(a[0]),"r"(a[1]),"r"(a[2]),"r"(a[3]),"r"(b[0]),"r"(b[1]));
}
__device__ __forceinline__ uint32_t swa(uint32_t base, int row, int u){
    return base + (uint32_t)row*128u + (uint32_t)(((u ^ (row & 7)) << 4));
}
__device__ __forceinline__ void split2(float x, float y, uint32_t &hi, uint32_t &lo){
    __nv_bfloat16 hx=__float2bfloat16(x), hy=__float2bfloat16(y);
    __nv_bfloat16 lx=__float2bfloat16(x-__bfloat162float(hx)), ly=__float2bfloat16(y-__bfloat162float(hy));
    hi = ((uint32_t)__bfloat16_as_ushort(hy)<<16)|__bfloat16_as_ushort(hx);
    lo = ((uint32_t)__bfloat16_as_ushort(ly)<<16)|__bfloat16_as_ushort(lx);
}
__device__ __forceinline__ void cvt_store(float4 v, char* smc, int offH, int offL, int row, int c4){
    uint32_t o = (uint32_t)row*128u + (uint32_t)(((((c4>>1) ^ (row&7)) << 4)) | ((c4&1)<<3));
    uint32_t h0, l0, h1, l1;
    split2(v.x, v.y, h0, l0);
    split2(v.z, v.w, h1, l1);
    *(uint2*)(smc + offH + o) = make_uint2(h0, h1);
    *(uint2*)(smc + offL + o) = make_uint2(l0, l1);
}

__global__ void __launch_bounds__(512, 1)
mha_hmma(const float* __restrict__ Kg, const float* __restrict__ Vg,
         const float* __restrict__ Qg, const int* __restrict__ Mg,
         const float* __restrict__ QMg, float* __restrict__ outR, float* __restrict__ outA)
{
    extern __shared__ char smc[];
    const uint32_t sb = s2u(smc);
    const int tid = threadIdx.x, wid = tid>>5, ln = tid&31;
    const int mt = wid>>1, h = wid&1;
    const int la = ln&3;
    const int r0 = 16*mt + (ln>>2), r1 = r0 + 8;
    const int b = blockIdx.x>>3, q0 = (blockIdx.x&7)*128;

    const int KH[2] = {OFF_K0H, OFF_K1H}, KL[2] = {OFF_K0L, OFF_K1L};
    const int VH[2] = {OFF_V0H, OFF_V1H}, VL[2] = {OFF_V0L, OFF_V1L};

    // ---- prologue: Q (x0.125) -> bf16 split; mask -> bitmask; K tile 0 -> buf0 ----
    const float4* gQ4 = (const float4*)(Qg + ((size_t)(b*1024 + q0))*64);
    for (int i = tid; i < 2048; i += 512){
        float4 v = gQ4[i];
        v.x*=0.125f; v.y*=0.125f; v.z*=0.125f; v.w*=0.125f;
        cvt_store(v, smc, OFF_QH, OFF_QL, i>>4, i&15);
    }
    uint32_t* mbm = (uint32_t*)(smc + OFF_MASK);
    const int* gM = Mg + ((size_t)(b*1024 + q0))*1024;
    for (int i = tid; i < 4096; i += 512){
        const int4* mp = (const int4*)(gM + ((size_t)(i>>5))*1024 + (i&31)*32);
        uint32_t bits = 0;
        #pragma unroll
        for (int m2 = 0; m2 < 8; m2++){
            int4 v = mp[m2];
            bits |= ((v.x?1u:0u)|(v.y?2u:0u)|(v.z?4u:0u)|(v.w?8u:0u)) << (4*m2);
        }
        mbm[i] = bits;
    }
    const float* gK = Kg + (size_t)b*65536;
    const float* gV = Vg + (size_t)b*65536;
    const float4* gK4 = (const float4*)gK;
    const float4* gV4 = (const float4*)gV;
    #pragma unroll
    for (int p = 0; p < 4; p++){
        int i = tid + p*512;
        cvt_store(gK4[i], smc, OFF_K0H, OFF_K0L, i>>4, i&15);
    }
    __syncthreads();

    // hoisted Q fragments (pass 1)
    const int qrow = 16*mt + (ln&15);
    uint32_t Qh[4][4], Ql[4][4];
    #pragma unroll
    for (int c = 0; c < 4; c++){
        ldsm4(Qh[c], swa(sb+OFF_QH, qrow, 2*c + (ln>>4)));
        ldsm4(Ql[c], swa(sb+OFF_QL, qrow, 2*c + (ln>>4)));
    }

    // ================= pass 1: masked rowsums (pipelined) =================
    float rs0 = 0.f, rs1 = 0.f;
    for (int t = 0; t < 8; t++){
        const int cur = t&1, nxt = cur^1;
        float4 pref[4];
        if (t < 7){
            const float4* g = gK4 + (size_t)(t+1)*2048;
            #pragma unroll
            for (int p = 0; p < 4; p++) pref[p] = g[tid + p*512];
        }
        float s[8][4];
        #pragma unroll
        for (int j=0;j<8;j++){ s[j][0]=0.f; s[j][1]=0.f; s[j][2]=0.f; s[j][3]=0.f; }
        #pragma unroll
        for (int c = 0; c < 4; c++){
            #pragma unroll
            for (int jp = 0; jp < 4; jp++){
                uint32_t bh[4], bl[4];
                int krow = 64*h + 16*jp + ((ln>>4)<<3) + (ln&7);
                int ku = 2*c + ((ln>>3)&1);
                ldsm4(bh, swa(sb+KH[cur], krow, ku));
                ldsm4(bl, swa(sb+KL[cur], krow, ku));
                mma_bf16(s[2*jp],   Qh[c], bh);   mma_bf16(s[2*jp],   Qh[c], bl);   mma_bf16(s[2*jp],   Ql[c], bh);
                mma_bf16(s[2*jp+1], Qh[c], bh+2); mma_bf16(s[2*jp+1], Qh[c], bl+2); mma_bf16(s[2*jp+1], Ql[c], bh+2);
            }
        }
        uint4 m0v = ((const uint4*)(mbm + r0*32))[t];
        uint4 m1v = ((const uint4*)(mbm + r1*32))[t];
        uint32_t w00 = h ? m0v.z : m0v.x, w01 = h ? m0v.w : m0v.y;
        uint32_t w10 = h ? m1v.z : m1v.x, w11 = h ? m1v.w : m1v.y;
        #pragma unroll
        for (int j = 0; j < 8; j++){
            uint32_t wr0 = (j<4)?w00:w01, wr1 = (j<4)?w10:w11;
            int bit = 8*(j&3) + 2*la;
            rs0 += ((wr0>>bit)&1u)     ? 0.f : __expf(s[j][0]);
            rs0 += ((wr0>>(bit+1))&1u) ? 0.f : __expf(s[j][1]);
            rs1 += ((wr1>>bit)&1u)     ? 0.f : __expf(s[j][2]);
            rs1 += ((wr1>>(bit+1))&1u) ? 0.f : __expf(s[j][3]);
        }
        if (t < 7){
            #pragma unroll
            for (int p = 0; p < 4; p++){
                int i = tid + p*512;
                cvt_store(pref[p], smc, KH[nxt], KL[nxt], i>>4, i&15);
            }
        }
        __syncthreads();
    }
    rs0 += __shfl_xor_sync(~0u, rs0, 1); rs0 += __shfl_xor_sync(~0u, rs0, 2);
    rs1 += __shfl_xor_sync(~0u, rs1, 1); rs1 += __shfl_xor_sync(~0u, rs1, 2);
    float* red = (float*)(smc + OFF_RED);
    if (la == 0){ red[h*128 + r0] = rs0; red[h*128 + r1] = rs1; }
    __syncthreads();
    if (tid < 128){
        float ssum = red[tid] + red[128+tid];
        float qm = QMg[(size_t)(b*1024 + q0 + tid)];
        ((float*)(smc+OFF_SCL))[tid] = (ssum>0.f) ? (qm/ssum) : 0.f;
        ((float*)(smc+OFF_UNI))[tid] = (ssum>0.f) ? 0.f : qm*(1.f/1024.f);
    }
    // reload K0 + V0 for pass 2 (buf0)
    #pragma unroll
    for (int p = 0; p < 4; p++){
        int i = tid + p*512;
        cvt_store(gK4[i], smc, OFF_K0H, OFF_K0L, i>>4, i&15);
        cvt_store(gV4[i], smc, OFF_V0H, OFF_V0L, i>>4, i&15);
    }
    __syncthreads();
    const float scl0 = ((float*)(smc+OFF_SCL))[r0], uad0 = ((float*)(smc+OFF_UNI))[r0];
    const float scl1 = ((float*)(smc+OFF_SCL))[r1], uad1 = ((float*)(smc+OFF_UNI))[r1];

    // ================= pass 2: attn + PV (pipelined) =================
    float o[8][4];
    #pragma unroll
    for (int j=0;j<8;j++){ o[j][0]=0.f; o[j][1]=0.f; o[j][2]=0.f; o[j][3]=0.f; }

    for (int t = 0; t < 8; t++){
        const int cur = t&1, nxt = cur^1;
        float4 pref[4];
        if (t < 7){
            const float4* g = gK4 + (size_t)(t+1)*2048;
            #pragma unroll
            for (int p = 0; p < 4; p++) pref[p] = g[tid + p*512];
        }
        float s[8][4];
        #pragma unroll
        for (int j=0;j<8;j++){ s[j][0]=0.f; s[j][1]=0.f; s[j][2]=0.f; s[j][3]=0.f; }
        #pragma unroll
        for (int c = 0; c < 4; c++){
            uint32_t qh[4], ql[4];
            ldsm4(qh, swa(sb+OFF_QH, qrow, 2*c + (ln>>4)));
            ldsm4(ql, swa(sb+OFF_QL, qrow, 2*c + (ln>>4)));
            #pragma unroll
            for (int jp = 0; jp < 4; jp++){
                uint32_t bh[4], bl[4];
                int krow = 64*h + 16*jp + ((ln>>4)<<3) + (ln&7);
                int ku = 2*c + ((ln>>3)&1);
                ldsm4(bh, swa(sb+KH[cur], krow, ku));
                ldsm4(bl, swa(sb+KL[cur], krow, ku));
                mma_bf16(s[2*jp],   qh, bh);   mma_bf16(s[2*jp],   qh, bl);   mma_bf16(s[2*jp],   ql, bh);
                mma_bf16(s[2*jp+1], qh, bh+2); mma_bf16(s[2*jp+1], qh, bl+2); mma_bf16(s[2*jp+1], ql, bh+2);
            }
        }
        if (t < 7){
            #pragma unroll
            for (int p = 0; p < 4; p++){
                int i = tid + p*512;
                cvt_store(pref[p], smc, KH[nxt], KL[nxt], i>>4, i&15);
            }
            const float4* g = gV4 + (size_t)(t+1)*2048;
            #pragma unroll
            for (int p = 0; p < 4; p++) pref[p] = g[tid + p*512];
        }
        // exp * scale (+ uniform for all-masked rows)
        {
            uint4 m0v = ((const uint4*)(mbm + r0*32))[t];
            uint4 m1v = ((const uint4*)(mbm + r1*32))[t];
            uint32_t w00 = h ? m0v.z : m0v.x, w01 = h ? m0v.w : m0v.y;
            uint32_t w10 = h ? m1v.z : m1v.x, w11 = h ? m1v.w : m1v.y;
            #pragma unroll
            for (int j = 0; j < 8; j++){
                uint32_t wr0 = (j<4)?w00:w01, wr1 = (j<4)?w10:w11;
                int bit = 8*(j&3) + 2*la;
                float p0 = ((wr0>>bit)&1u)     ? 0.f : __expf(s[j][0]);
                float p1 = ((wr0>>(bit+1))&1u) ? 0.f : __expf(s[j][1]);
                float p2 = ((wr1>>bit)&1u)     ? 0.f : __expf(s[j][2]);
                float p3 = ((wr1>>(bit+1))&1u) ? 0.f : __expf(s[j][3]);
                s[j][0] = p0*scl0 + uad0;  s[j][1] = p1*scl0 + uad0;
                s[j][2] = p2*scl1 + uad1;  s[j][3] = p3*scl1 + uad1;
            }
        }
        // attn store
        {
            float* a0p = outA + ((size_t)(b*1024+q0+r0))*1024 + t*128 + 64*h + 2*la;
            float* a1p = outA + ((size_t)(b*1024+q0+r1))*1024 + t*128 + 64*h + 2*la;
            #pragma unroll
            for (int j=0;j<8;j++){
                *(float2*)(a0p + 8*j) = make_float2(s[j][0], s[j][1]);
                *(float2*)(a1p + 8*j) = make_float2(s[j][2], s[j][3]);
            }
        }
        // PV: per-chunk A fragments (8 regs)
        #pragma unroll
        for (int c=0;c<4;c++){
            uint32_t ah[4], al[4];
            split2(s[2*c][0],   s[2*c][1],   ah[0], al[0]);
            split2(s[2*c][2],   s[2*c][3],   ah[1], al[1]);
            split2(s[2*c+1][0], s[2*c+1][1], ah[2], al[2]);
            split2(s[2*c+1][2], s[2*c+1][3], ah[3], al[3]);
            #pragma unroll
            for (int jp=0;jp<4;jp++){
                uint32_t bh[4], bl[4];
                int vrow = 64*h + 16*c + ((ln>>3)&1)*8 + (ln&7);
                int vu = 2*jp + (ln>>4);
                ldsm4t(bh, swa(sb+VH[cur], vrow, vu));
                ldsm4t(bl, swa(sb+VL[cur], vrow, vu));
                mma_bf16(o[2*jp],   ah, bh);   mma_bf16(o[2*jp],   ah, bl);   mma_bf16(o[2*jp],   al, bh);
                mma_bf16(o[2*jp+1], ah, bh+2); mma_bf16(o[2*jp+1], ah, bl+2); mma_bf16(o[2*jp+1], al, bh+2);
            }
        }
        if (t < 7){
            #pragma unroll
            for (int p = 0; p < 4; p++){
                int i = tid + p*512;
                cvt_store(pref[p], smc, VH[nxt], VL[nxt], i>>4, i&15);
            }
        }
        __syncthreads();
    }

    // ---- combine k-halves, store result ----
    float* Os = (float*)(smc + OFF_OST);
    if (h == 0){
        #pragma unroll
        for (int j=0;j<8;j++){
            *(float2*)(Os + r0*64 + 8*j + 2*la) = make_float2(o[j][0], o[j][1]);
            *(float2*)(Os + r1*64 + 8*j + 2*la) = make_float2(o[j][2], o[j][3]);
        }
    }
    __syncthreads();
    if (h == 1){
        float* oR = outR + ((size_t)(b*1024+q0))*64;
        #pragma unroll
        for (int j=0;j<8;j++){
            float2 a0 = *(float2*)(Os + r0*64 + 8*j + 2*la);
            float2 a1 = *(float2*)(Os + r1*64 + 8*j + 2*la);
            *(float2*)(oR + (size_t)r0*64 + 8*j + 2*la) = make_float2(a0.x+o[j][0], a0.y+o[j][1]);
            *(float2*)(oR + (size_t)r1*64 + 8*j + 2*la) = make_float2(a1.x+o[j][2], a1.y+o[j][3]);
        }
    }
}

extern "C" void kernel_launch(void* const* d_in, const int* in_sizes, int n_in,
                              void* d_out, int out_size)
{
    const float* Kg  = (const float*)d_in[0];
    const float* Vg  = (const float*)d_in[1];
    const float* Qg  = (const float*)d_in[2];
    const int*   Mg  = (const int*)d_in[3];
    const float* QMg = (const float*)d_in[4];
    float* outR = (float*)d_out;
    float* outA = outR + (size_t)B_ * 1024 * 64;
    cudaFuncSetAttribute(mha_hmma, cudaFuncAttributeMaxDynamicSharedMemorySize, SMEM_TOTAL);
    mha_hmma<<<B_ * 8, 512, SMEM_TOTAL>>>(Kg, Vg, Qg, Mg, QMg, outR, outA);
}